// round 1
// baseline (speedup 1.0000x reference)
#include <cuda_runtime.h>
#include <cuda_bf16.h>
#include <float.h>

// Problem: out[b][c] = max over (h,w) of in[b][h][w][c]
//   in : [32, 224, 224, 128] f32, NHWC (C contiguous)
//   out: [32, 128] f32
// Pure HBM-streaming reduction: 822 MB read, 16 KB written.

static constexpr int B  = 32;
static constexpr int HW = 224 * 224;   // 50176 spatial rows per batch
static constexpr int C  = 128;         // channels (contiguous)
static constexpr int C4 = C / 4;       // 32 float4 groups per row

static constexpr int THREADS = 256;    // 32 c4-lanes x 8 row-lanes
static constexpr int ROWS_PER_BLK = THREADS / C4;  // 8
static constexpr int GRID_X = 37;      // 37*32 = 1184 blocks = 8/SM * 148 SMs (one full wave)

__device__ __forceinline__ float4 f4max(float4 a, float4 b) {
    return make_float4(fmaxf(a.x, b.x), fmaxf(a.y, b.y),
                       fmaxf(a.z, b.z), fmaxf(a.w, b.w));
}

// Float atomic-max via monotone int/uint reinterpretation.
// Valid for any finite floats given init = -FLT_MAX.
__device__ __forceinline__ void atomicMaxF(float* addr, float v) {
    if (v >= 0.0f) {
        atomicMax(reinterpret_cast<int*>(addr), __float_as_int(v));
    } else {
        atomicMin(reinterpret_cast<unsigned int*>(addr), __float_as_uint(v));
    }
}

__global__ void init_out_kernel(float* __restrict__ out, int n) {
    int i = blockIdx.x * blockDim.x + threadIdx.x;
    if (i < n) out[i] = -FLT_MAX;
}

__global__ __launch_bounds__(THREADS, 8)
void max_spatial_kernel(const float* __restrict__ in, float* __restrict__ out) {
    const int b   = blockIdx.y;
    const int c4  = threadIdx.x & (C4 - 1);   // float4 channel group 0..31
    const int r   = threadIdx.x >> 5;         // row lane 0..7

    // Base pointer for this batch + channel group (float4 units)
    const float4* base =
        reinterpret_cast<const float4*>(in + (size_t)b * HW * C) + c4;

    const int stride = GRID_X * ROWS_PER_BLK;   // 296 rows
    int row = blockIdx.x * ROWS_PER_BLK + r;

    float4 m0 = make_float4(-FLT_MAX, -FLT_MAX, -FLT_MAX, -FLT_MAX);
    float4 m1 = m0, m2 = m0, m3 = m0;

    // 4-way unrolled main loop: 4 independent LDG.128 in flight (MLP>=4)
    for (; row + 3 * stride < HW; row += 4 * stride) {
        float4 v0 = __ldg(base + (size_t)(row             ) * C4);
        float4 v1 = __ldg(base + (size_t)(row +     stride) * C4);
        float4 v2 = __ldg(base + (size_t)(row + 2 * stride) * C4);
        float4 v3 = __ldg(base + (size_t)(row + 3 * stride) * C4);
        m0 = f4max(m0, v0);
        m1 = f4max(m1, v1);
        m2 = f4max(m2, v2);
        m3 = f4max(m3, v3);
    }
    for (; row < HW; row += stride) {
        m0 = f4max(m0, __ldg(base + (size_t)row * C4));
    }
    float4 m = f4max(f4max(m0, m1), f4max(m2, m3));

    // Reduce across the 8 row-lanes sharing this c4 (tid, tid+32, ... tid+224)
    __shared__ float4 sm[THREADS];
    sm[threadIdx.x] = m;
    __syncthreads();
    if (threadIdx.x < 128) sm[threadIdx.x] = f4max(sm[threadIdx.x], sm[threadIdx.x + 128]);
    __syncthreads();
    if (threadIdx.x < 64)  sm[threadIdx.x] = f4max(sm[threadIdx.x], sm[threadIdx.x + 64]);
    __syncthreads();
    if (threadIdx.x < 32) {
        float4 v = f4max(sm[threadIdx.x], sm[threadIdx.x + 32]);
        float* o = out + b * C + threadIdx.x * 4;
        atomicMaxF(o + 0, v.x);
        atomicMaxF(o + 1, v.y);
        atomicMaxF(o + 2, v.z);
        atomicMaxF(o + 3, v.w);
    }
}

extern "C" void kernel_launch(void* const* d_in, const int* in_sizes, int n_in,
                              void* d_out, int out_size) {
    const float* in = (const float*)d_in[0];
    float* out = (float*)d_out;

    init_out_kernel<<<(out_size + 255) / 256, 256>>>(out, out_size);

    dim3 grid(GRID_X, B);
    max_spatial_kernel<<<grid, THREADS>>>(in, out);
}

// round 2
// speedup vs baseline: 1.2443x; 1.2443x over previous
#include <cuda_runtime.h>
#include <cuda_bf16.h>
#include <float.h>

// Problem: out[b][c] = max over (h,w) of in[b][h][w][c]
//   in : [32, 224, 224, 128] f32, NHWC (C contiguous)
//   out: [32, 128] f32
// Pure HBM-streaming reduction: 822 MB read, 16 KB written.

static constexpr int B  = 32;
static constexpr int HW = 224 * 224;   // 50176 spatial rows per batch
static constexpr int C  = 128;         // channels (contiguous)
static constexpr int C4 = C / 4;       // 32 float4 groups per row

static constexpr int THREADS = 256;    // 32 c4-lanes x 8 row-lanes
static constexpr int ROWS_PER_BLK = THREADS / C4;  // 8
static constexpr int GRID_X = 37;      // 37*32 = 1184 blocks total (2 waves @ occ 4)
static constexpr int STRIDE = GRID_X * ROWS_PER_BLK;  // 296 rows
static constexpr int UNROLL = 8;

__device__ __forceinline__ float4 f4max(float4 a, float4 b) {
    return make_float4(fmaxf(a.x, b.x), fmaxf(a.y, b.y),
                       fmaxf(a.z, b.z), fmaxf(a.w, b.w));
}

// Float atomic-max via monotone int/uint reinterpretation.
// Valid for any finite floats given init = -FLT_MAX.
__device__ __forceinline__ void atomicMaxF(float* addr, float v) {
    if (v >= 0.0f) {
        atomicMax(reinterpret_cast<int*>(addr), __float_as_int(v));
    } else {
        atomicMin(reinterpret_cast<unsigned int*>(addr), __float_as_uint(v));
    }
}

__global__ void init_out_kernel(float* __restrict__ out, int n) {
    int i = blockIdx.x * blockDim.x + threadIdx.x;
    if (i < n) out[i] = -FLT_MAX;
}

__global__ __launch_bounds__(THREADS, 4)   // allow ~64 regs -> real MLP
void max_spatial_kernel(const float* __restrict__ in, float* __restrict__ out) {
    const int b   = blockIdx.y;
    const int c4  = threadIdx.x & (C4 - 1);   // float4 channel group 0..31
    const int r   = threadIdx.x >> 5;         // row lane 0..7

    // Base pointer for this batch + channel group (float4 units)
    const float4* base =
        reinterpret_cast<const float4*>(in + (size_t)b * HW * C) + c4;

    int row = blockIdx.x * ROWS_PER_BLK + r;

    float4 m[UNROLL];
    #pragma unroll
    for (int i = 0; i < UNROLL; i++)
        m[i] = make_float4(-FLT_MAX, -FLT_MAX, -FLT_MAX, -FLT_MAX);

    // 8-way unrolled main loop: 8 independent streaming LDG.128 in flight.
    // __ldcs = evict-first: data is single-use, don't thrash L2.
    for (; row + (UNROLL - 1) * STRIDE < HW; row += UNROLL * STRIDE) {
        float4 v[UNROLL];
        #pragma unroll
        for (int i = 0; i < UNROLL; i++)
            v[i] = __ldcs(base + (size_t)(row + i * STRIDE) * C4);
        #pragma unroll
        for (int i = 0; i < UNROLL; i++)
            m[i] = f4max(m[i], v[i]);
    }
    for (; row < HW; row += STRIDE) {
        m[0] = f4max(m[0], __ldcs(base + (size_t)row * C4));
    }

    // Tree-combine the 8 accumulators
    #pragma unroll
    for (int s = UNROLL / 2; s > 0; s >>= 1)
        #pragma unroll
        for (int i = 0; i < s; i++)
            m[i] = f4max(m[i], m[i + s]);

    // Reduce across the 8 row-lanes sharing this c4 (tid, tid+32, ... tid+224)
    __shared__ float4 sm[THREADS];
    sm[threadIdx.x] = m[0];
    __syncthreads();
    if (threadIdx.x < 128) sm[threadIdx.x] = f4max(sm[threadIdx.x], sm[threadIdx.x + 128]);
    __syncthreads();
    if (threadIdx.x < 64)  sm[threadIdx.x] = f4max(sm[threadIdx.x], sm[threadIdx.x + 64]);
    __syncthreads();
    if (threadIdx.x < 32) {
        float4 v = f4max(sm[threadIdx.x], sm[threadIdx.x + 32]);
        float* o = out + b * C + threadIdx.x * 4;
        atomicMaxF(o + 0, v.x);
        atomicMaxF(o + 1, v.y);
        atomicMaxF(o + 2, v.z);
        atomicMaxF(o + 3, v.w);
    }
}

extern "C" void kernel_launch(void* const* d_in, const int* in_sizes, int n_in,
                              void* d_out, int out_size) {
    const float* in = (const float*)d_in[0];
    float* out = (float*)d_out;

    init_out_kernel<<<(out_size + 255) / 256, 256>>>(out, out_size);

    dim3 grid(GRID_X, B);
    max_spatial_kernel<<<grid, THREADS>>>(in, out);
}

// round 3
// speedup vs baseline: 1.2846x; 1.0324x over previous
#include <cuda_runtime.h>
#include <cuda_bf16.h>
#include <float.h>

// Problem: out[b][c] = max over (h,w) of in[b][h][w][c]
//   in : [32, 224, 224, 128] f32, NHWC (C contiguous)
//   out: [32, 128] f32
// Pure HBM-streaming reduction: 822 MB read, 16 KB written.

static constexpr int B  = 32;
static constexpr int HW = 224 * 224;   // 50176 spatial rows per batch
static constexpr int C  = 128;         // channels (contiguous)
static constexpr int C4 = C / 4;       // 32 float4 groups per row

static constexpr int THREADS = 256;    // 32 c4-lanes x 8 row-lanes
static constexpr int ROWS_PER_BLK = THREADS / C4;  // 8
static constexpr int GRID_X = 37;      // 37*32 = 1184 blocks total (2 waves @ occ 4)
static constexpr int STRIDE = GRID_X * ROWS_PER_BLK;  // 296 rows
static constexpr int UNROLL = 8;

__device__ __forceinline__ float4 f4max(float4 a, float4 b) {
    return make_float4(fmaxf(a.x, b.x), fmaxf(a.y, b.y),
                       fmaxf(a.z, b.z), fmaxf(a.w, b.w));
}

// Float atomic-max via monotone int/uint reinterpretation.
// Valid for any finite floats given init = -FLT_MAX.
__device__ __forceinline__ void atomicMaxF(float* addr, float v) {
    if (v >= 0.0f) {
        atomicMax(reinterpret_cast<int*>(addr), __float_as_int(v));
    } else {
        atomicMin(reinterpret_cast<unsigned int*>(addr), __float_as_uint(v));
    }
}

__global__ void init_out_kernel(float* __restrict__ out, int n) {
    int i = blockIdx.x * blockDim.x + threadIdx.x;
    if (i < n) out[i] = -FLT_MAX;
}

__global__ __launch_bounds__(THREADS, 4)   // allow ~64 regs -> real MLP
void max_spatial_kernel(const float* __restrict__ in, float* __restrict__ out) {
    const int b   = blockIdx.y;
    const int c4  = threadIdx.x & (C4 - 1);   // float4 channel group 0..31
    const int r   = threadIdx.x >> 5;         // row lane 0..7

    // Base pointer for this batch + channel group (float4 units)
    const float4* base =
        reinterpret_cast<const float4*>(in + (size_t)b * HW * C) + c4;

    int row = blockIdx.x * ROWS_PER_BLK + r;

    float4 m[UNROLL];
    #pragma unroll
    for (int i = 0; i < UNROLL; i++)
        m[i] = make_float4(-FLT_MAX, -FLT_MAX, -FLT_MAX, -FLT_MAX);

    // 8-way unrolled main loop: 8 independent streaming LDG.128 in flight.
    // __ldcs = evict-first: data is single-use, don't thrash L2.
    for (; row + (UNROLL - 1) * STRIDE < HW; row += UNROLL * STRIDE) {
        float4 v[UNROLL];
        #pragma unroll
        for (int i = 0; i < UNROLL; i++)
            v[i] = __ldcs(base + (size_t)(row + i * STRIDE) * C4);
        #pragma unroll
        for (int i = 0; i < UNROLL; i++)
            m[i] = f4max(m[i], v[i]);
    }
    for (; row < HW; row += STRIDE) {
        m[0] = f4max(m[0], __ldcs(base + (size_t)row * C4));
    }

    // Tree-combine the 8 accumulators
    #pragma unroll
    for (int s = UNROLL / 2; s > 0; s >>= 1)
        #pragma unroll
        for (int i = 0; i < s; i++)
            m[i] = f4max(m[i], m[i + s]);

    // Reduce across the 8 row-lanes sharing this c4 (tid, tid+32, ... tid+224)
    __shared__ float4 sm[THREADS];
    sm[threadIdx.x] = m[0];
    __syncthreads();
    if (threadIdx.x < 128) sm[threadIdx.x] = f4max(sm[threadIdx.x], sm[threadIdx.x + 128]);
    __syncthreads();
    if (threadIdx.x < 64)  sm[threadIdx.x] = f4max(sm[threadIdx.x], sm[threadIdx.x + 64]);
    __syncthreads();
    if (threadIdx.x < 32) {
        float4 v = f4max(sm[threadIdx.x], sm[threadIdx.x + 32]);
        float* o = out + b * C + threadIdx.x * 4;
        atomicMaxF(o + 0, v.x);
        atomicMaxF(o + 1, v.y);
        atomicMaxF(o + 2, v.z);
        atomicMaxF(o + 3, v.w);
    }
}

extern "C" void kernel_launch(void* const* d_in, const int* in_sizes, int n_in,
                              void* d_out, int out_size) {
    const float* in = (const float*)d_in[0];
    float* out = (float*)d_out;

    init_out_kernel<<<(out_size + 255) / 256, 256>>>(out, out_size);

    dim3 grid(GRID_X, B);
    max_spatial_kernel<<<grid, THREADS>>>(in, out);
}